// round 14
// baseline (speedup 1.0000x reference)
#include <cuda_runtime.h>
#include <cuda_fp16.h>
#include <mma.h>
#include <math.h>
#include <stdint.h>

using namespace nvcuda;

#define Bdim  4
#define Sdim  2048
#define Ddim  2048
#define Edim  8
#define HDdim 256
#define F3    768
#define KMAXd 2048
#define EB    (Edim*Bdim)

typedef __half f16;

// ---------------- scratch (device globals; no allocations allowed) ----------
__device__ f16   g_qkvh[(size_t)EB * KMAXd * F3];  // post-rope [qf|kf|v] fp16
__device__ f16   g_ctxh[(size_t)EB * KMAXd * HDdim];
__device__ f16   g_Xh[(size_t)Bdim * Sdim * Ddim];
__device__ f16   g_Wqh[(size_t)Edim * Ddim * F3];
__device__ f16   g_Wfh[(size_t)Edim * HDdim * Ddim];
__device__ float g_tcos[KMAXd * 512];
__device__ float g_tsin[KMAXd * 512];
__device__ int   g_sid[EB * KMAXd];
__device__ int   g_cnt[EB];
__device__ int   g_maxlen;
__device__ unsigned char g_emask[Bdim * Sdim];

// ---------------- cp.async helpers ------------------------------------------
__device__ __forceinline__ void cpa16(void* smem, const void* gmem)
{
    uint32_t s = (uint32_t)__cvta_generic_to_shared(smem);
    asm volatile("cp.async.cg.shared.global [%0], [%1], 16;\n" :: "r"(s), "l"(gmem));
}
#define CP_COMMIT() asm volatile("cp.async.commit_group;\n" ::: "memory")
#define CP_WAIT(n)  asm volatile("cp.async.wait_group %0;\n" :: "n"(n) : "memory")

// ---------------- 0b) fp32 -> fp16 single (weights) ---------------------------
__global__ void k_cvtH(const float* __restrict__ src, f16* __restrict__ h, size_t n4)
{
    size_t i = (size_t)blockIdx.x * blockDim.x + threadIdx.x;
    if (i >= n4) return;
    float4 v = reinterpret_cast<const float4*>(src)[i];
    __half2 h01 = __floats2half2_rn(v.x, v.y);
    __half2 h23 = __floats2half2_rn(v.z, v.w);
    reinterpret_cast<uint2*>(h)[i] = make_uint2(*(uint32_t*)&h01, *(uint32_t*)&h23);
}

// ---------------- 0c) rope tables (only K_len rows; fp32 sincos) -------------
__global__ void k_rtab()
{
    int k = blockIdx.x;
    if (k >= g_maxlen) return;
    int j = threadIdx.x;
    double freq = exp(((double)(-2 * j) / 1024.0) * log(10000.0));
    float ang = (float)k * (float)freq;
    float ss, cc;
    sincosf(ang, &ss, &cc);
    g_tcos[k * 512 + j] = cc;
    g_tsin[k * 512 + j] = ss;
}

// ---------------- 1) gate logits + top-2 mask + fused X->fp16 (float4) -------
__global__ void k_gate(const float* __restrict__ X,
                       const float* __restrict__ wg,
                       const float* __restrict__ bg,
                       f16* __restrict__ xh)
{
    int bs = blockIdx.x;
    const float4* xr = (const float4*)(X + (size_t)bs * Ddim);
    f16* xo = xh + (size_t)bs * Ddim;
    float acc[8];
#pragma unroll
    for (int e = 0; e < 8; e++) acc[e] = 0.f;
#pragma unroll
    for (int i = 0; i < 4; i++) {
        int d4 = threadIdx.x + i * 128;
        float4 xv = xr[d4];
        int d = d4 * 4;
        __half2 h01 = __floats2half2_rn(xv.x, xv.y);
        __half2 h23 = __floats2half2_rn(xv.z, xv.w);
        *(uint2*)&xo[d] = make_uint2(*(uint32_t*)&h01, *(uint32_t*)&h23);
        float xs[4] = {xv.x, xv.y, xv.z, xv.w};
        const float4* w = (const float4*)(wg + (size_t)d * Edim);
#pragma unroll
        for (int r = 0; r < 4; r++) {
            float4 w0 = w[2 * r], w1 = w[2 * r + 1];
            acc[0] = fmaf(xs[r], w0.x, acc[0]); acc[1] = fmaf(xs[r], w0.y, acc[1]);
            acc[2] = fmaf(xs[r], w0.z, acc[2]); acc[3] = fmaf(xs[r], w0.w, acc[3]);
            acc[4] = fmaf(xs[r], w1.x, acc[4]); acc[5] = fmaf(xs[r], w1.y, acc[5]);
            acc[6] = fmaf(xs[r], w1.z, acc[6]); acc[7] = fmaf(xs[r], w1.w, acc[7]);
        }
    }
#pragma unroll
    for (int e = 0; e < 8; e++)
#pragma unroll
        for (int off = 16; off; off >>= 1)
            acc[e] += __shfl_down_sync(0xffffffffu, acc[e], off);

    __shared__ float red[4][8];
    int wid = threadIdx.x >> 5, lane = threadIdx.x & 31;
    if (lane == 0) {
#pragma unroll
        for (int e = 0; e < 8; e++) red[wid][e] = acc[e];
    }
    __syncthreads();
    if (threadIdx.x == 0) {
        float v[8];
#pragma unroll
        for (int e = 0; e < 8; e++)
            v[e] = red[0][e] + red[1][e] + red[2][e] + red[3][e] + bg[e];
        int e1 = 0; float b1 = v[0];
#pragma unroll
        for (int e = 1; e < 8; e++) if (v[e] > b1) { b1 = v[e]; e1 = e; }
        int e2 = -1; float b2 = -3.0e38f;
#pragma unroll
        for (int e = 0; e < 8; e++) if (e != e1 && v[e] > b2) { b2 = v[e]; e2 = e; }
        g_emask[bs] = (unsigned char)((1u << e1) | (1u << e2));
    }
}

// ---------------- 2) per-(e,b) member counts + global max -------------------
__global__ void k_count()
{
    int eb = blockIdx.x; int e = eb / Bdim, b = eb % Bdim;
    int n = 0;
    for (int s = threadIdx.x; s < Sdim; s += 256)
        n += (g_emask[b * Sdim + s] >> e) & 1;
#pragma unroll
    for (int off = 16; off; off >>= 1) n += __shfl_down_sync(0xffffffffu, n, off);
    __shared__ int sm[8];
    int wid = threadIdx.x >> 5, lane = threadIdx.x & 31;
    if (lane == 0) sm[wid] = n;
    __syncthreads();
    if (threadIdx.x == 0) {
        int t = 0;
#pragma unroll
        for (int w = 0; w < 8; w++) t += sm[w];
        g_cnt[eb] = t;
        atomicMax(&g_maxlen, t);
    }
}

// ---------------- 3) build seq_ids ------------------------------------------
__global__ void k_build()
{
    int eb = blockIdx.x; int e = eb / Bdim, b = eb % Bdim;
    int pad = g_maxlen - g_cnt[eb];
    __shared__ int wsum[8];
    __shared__ int carry;
    if (threadIdx.x == 0) carry = 0;
    __syncthreads();
    int wid = threadIdx.x >> 5, lane = threadIdx.x & 31;
    for (int s0 = 0; s0 < Sdim; s0 += 256) {
        int s = s0 + threadIdx.x;
        int m = (g_emask[b * Sdim + s] >> e) & 1;
        unsigned bal = __ballot_sync(0xffffffffu, m);
        int mp_w = __popc(bal & ((1u << lane) - 1u));
        if (lane == 0) wsum[wid] = __popc(bal);
        __syncthreads();
        int pre = 0;
#pragma unroll
        for (int w = 0; w < 8; w++) if (w < wid) pre += wsum[w];
        int mp  = carry + pre + mp_w;
        int nmb = s - mp;
        bool sel = m || (nmb < pad);
        int pos  = mp + min(nmb, pad);
        if (sel) g_sid[eb * KMAXd + pos] = s;
        __syncthreads();
        if (threadIdx.x == 0) {
            int t = 0;
#pragma unroll
            for (int w = 0; w < 8; w++) t += wsum[w];
            carry += t;
        }
        __syncthreads();
    }
}

// ---------------- GEMM machinery: C[64x128], A & B single fp16, 2-stage ------
#define APITCH 40
#define BPITCH 136
#define CPITCH 132
#define GSTAGE 13824
#define SRAW_BYTES (64 * CPITCH * 4)

struct GT { f16 *A, *Bh; };
__device__ __forceinline__ GT gstage(unsigned char* base, int s)
{
    unsigned char* p = base + s * GSTAGE;
    GT t; t.A = (f16*)p; t.Bh = (f16*)(p + 5120);
    return t;
}

__device__ __forceinline__ void g_issue(
    GT t, int tid, const f16* __restrict__ Ag, const int* rows, int astr, int k0,
    const f16* __restrict__ Bhg, int bstr, int col0)
{
    {
        int row = tid >> 2, c8 = (tid & 3) * 8;
        cpa16(&t.A[row * APITCH + c8], Ag + (size_t)rows[row] * astr + k0 + c8);
    }
#pragma unroll
    for (int it = 0; it < 2; it++) {
        int idx = tid + it * 256;
        int row = idx >> 4, c8 = (idx & 15) * 8;
        cpa16(&t.Bh[row * BPITCH + c8], Bhg + (size_t)(k0 + row) * bstr + col0 + c8);
    }
}

__device__ __forceinline__ void g_comp(
    GT t, int wr, int wc,
    wmma::fragment<wmma::accumulator, 16, 16, 16, float> (&acc)[2][2])
{
#pragma unroll
    for (int kk = 0; kk < 32; kk += 16) {
        wmma::fragment<wmma::matrix_a, 16, 16, 16, half, wmma::row_major> a[2];
        wmma::fragment<wmma::matrix_b, 16, 16, 16, half, wmma::row_major> bh[2];
#pragma unroll
        for (int i = 0; i < 2; i++)
            wmma::load_matrix_sync(a[i], &t.A[(wr * 32 + i * 16) * APITCH + kk], APITCH);
#pragma unroll
        for (int j = 0; j < 2; j++)
            wmma::load_matrix_sync(bh[j], &t.Bh[kk * BPITCH + wc * 32 + j * 16], BPITCH);
#pragma unroll
        for (int i = 0; i < 2; i++)
#pragma unroll
            for (int j = 0; j < 2; j++)
                wmma::mma_sync(acc[i][j], a[i], bh[j], acc[i][j]);
    }
}

// ---------------- 4) QKV GEMM + fused rope epilogue (fp16 out) ----------------
__global__ void __launch_bounds__(256) k_qkv(const float* __restrict__ bq)
{
    int K_len = g_maxlen;
    int row0 = blockIdx.y * 64; if (row0 >= K_len) return;
    int eb = blockIdx.z; int e = eb / Bdim, b = eb % Bdim;
    int col0 = blockIdx.x * 128;

    __shared__ __align__(16) unsigned char sraw[SRAW_BYTES];
    __shared__ int sids[64];
    float* Cs = (float*)sraw;

    int tid = threadIdx.x;
    if (tid < 64) sids[tid] = g_sid[eb * KMAXd + min(row0 + tid, K_len - 1)];
    __syncthreads();

    int wid = tid >> 5;
    int wr = wid >> 2, wc = wid & 3;

    wmma::fragment<wmma::accumulator, 16, 16, 16, float> acc[2][2];
#pragma unroll
    for (int i = 0; i < 2; i++)
#pragma unroll
        for (int j = 0; j < 2; j++) wmma::fill_fragment(acc[i][j], 0.f);

    const f16* Ag  = g_Xh + (size_t)b * Sdim * Ddim;
    const f16* Bhg = g_Wqh + (size_t)e * Ddim * F3;
    const int T = Ddim / 32;

    g_issue(gstage(sraw, 0), tid, Ag, sids, Ddim, 0, Bhg, F3, col0);
    CP_COMMIT();
    for (int t = 0; t < T; t++) {
        if (t + 1 < T) {
            g_issue(gstage(sraw, (t + 1) & 1), tid, Ag, sids, Ddim, (t + 1) * 32,
                    Bhg, F3, col0);
            CP_COMMIT();
            CP_WAIT(1);
        } else {
            CP_WAIT(0);
        }
        __syncthreads();
        g_comp(gstage(sraw, t & 1), wr, wc, acc);
        __syncthreads();
    }

#pragma unroll
    for (int i = 0; i < 2; i++)
#pragma unroll
        for (int j = 0; j < 2; j++)
            wmma::store_matrix_sync(&Cs[(wr * 32 + i * 16) * CPITCH + wc * 32 + j * 16],
                                    acc[i][j], CPITCH, wmma::mem_row_major);
    __syncthreads();

    // fused: bias + rope + fp16 convert, with nope/pe half swap
    int blk = col0 >> 8;               // 0=q, 1=k, 2=v
    int halfsel = (col0 >> 7) & 1;
    int obase = blk * 256;
    const float* bqe = bq + e * F3 + col0;
    for (int idx = tid; idx < 64 * 64; idx += 256) {
        int r = idx >> 6, p = idx & 63;
        int grow = row0 + r;
        if (grow >= K_len) continue;
        float v0 = Cs[r * CPITCH + 2 * p]     + bqe[2 * p];
        float v1 = Cs[r * CPITCH + 2 * p + 1] + bqe[2 * p + 1];
        int outc;
        if (blk == 2) {
            outc = col0 + 2 * p;
        } else if (halfsel == 0) {
            outc = obase + 128 + 2 * p;
        } else {
            int ti = grow * 512 + e * 64 + p;
            float c = g_tcos[ti], s = g_tsin[ti];
            float r0 = v0 * c - v1 * s;
            float r1 = v0 * s + v1 * c;
            v0 = r0; v1 = r1;
            outc = obase + 2 * p;
        }
        size_t off = ((size_t)eb * KMAXd + grow) * F3 + outc;
        *(__half2*)&g_qkvh[off] = __floats2half2_rn(v0, v1);
    }
}

// ---------------- 5) attention: single-pass, no-max softmax, cp.async --------
// layout: Q@0 (33792) | K@33792 (16896) | V@50688 (16896) | S@67584 (9216)
//         | mt@76800 (128) | P@76928 (5120) -> total 82048; Ost aliases @0
#define QT 64
#define KT 32
#define QP 264
#define KP 264
#define SP 36
#define PP 40
#define OP 260
#define AQ   0
#define AKH  33792
#define AVH  50688
#define AS   67584
#define AMT  76800
#define APH  76928
#define ATTN_SMEM 82048

__global__ void __launch_bounds__(256) k_attn2(const float* __restrict__ mask)
{
    extern __shared__ unsigned char dsm[];
    int K_len = g_maxlen;
    int q0 = blockIdx.x * QT; if (q0 >= K_len) return;
    int eb = blockIdx.y; int b = eb % Bdim;
    int tid = threadIdx.x, wid = tid >> 5;
    int rg = wid & 3, cg = wid >> 2;

    f16* Qh = (f16*)(dsm + AQ);
    f16* Kh = (f16*)(dsm + AKH);
    f16* Vh = (f16*)(dsm + AVH);
    float* Ssm = (float*)(dsm + AS);
    float* mt  = (float*)(dsm + AMT);
    f16* Ph = (f16*)(dsm + APH);
    float* Ost = (float*)dsm;          // epilogue alias (post-loop only)

    const size_t rowbase = (size_t)eb * KMAXd;
    const f16* qkv = g_qkvh + rowbase * F3;

    // Q tile 64 x 256 (cp.async, group 0)
    {
        const f16* qh = qkv + (size_t)q0 * F3;
#pragma unroll
        for (int it = 0; it < 8; it++) {
            int idx = tid + it * 256;
            int r = idx >> 5, c8 = (idx & 31) * 8;
            cpa16(&Qh[r * QP + c8], &qh[(size_t)r * F3 + c8]);
        }
    }
    CP_COMMIT();
    // K tile 0
    {
#pragma unroll
        for (int it = 0; it < 4; it++) {
            int idx = tid + it * 256;
            int r = idx >> 5, c8 = (idx & 31) * 8;
            cpa16(&Kh[r * KP + c8], &qkv[(size_t)r * F3 + 256 + c8]);
        }
    }
    CP_COMMIT();

    int NT = (K_len + KT - 1) / KT;
    int rrow = tid >> 2, cbase = (tid & 3) * 8;
    float l_run = 0.f;
    wmma::fragment<wmma::accumulator, 16, 16, 16, float> of[8];
#pragma unroll
    for (int j = 0; j < 8; j++) wmma::fill_fragment(of[j], 0.f);

    for (int kt = 0; kt < NT; kt++) {
        if (tid < KT) {
            int k = kt * KT + tid;
            mt[tid] = (k < K_len)
                ? -1000000.0f * (1.0f - mask[b * Sdim + g_sid[eb * KMAXd + k]])
                : -1.0e30f;
        }
        CP_WAIT(0);              // Q (first iter) + current K resident
        __syncthreads();         // B1: K/mt visible; prev Vh/Ssm consumers done
        // issue V_kt (overlaps S MMA + exp)
        {
            const f16* vh = qkv + (size_t)kt * KT * F3 + 512;
#pragma unroll
            for (int it = 0; it < 4; it++) {
                int idx = tid + it * 256;
                int r = idx >> 5, c8 = (idx & 31) * 8;
                cpa16(&Vh[r * KP + c8], &vh[(size_t)r * F3 + c8]);
            }
        }
        CP_COMMIT();
        // S = Q @ K^T
        {
            wmma::fragment<wmma::accumulator, 16, 16, 16, float> sf;
            wmma::fill_fragment(sf, 0.f);
#pragma unroll
            for (int k16 = 0; k16 < 256; k16 += 16) {
                wmma::fragment<wmma::matrix_a, 16, 16, 16, half, wmma::row_major> ah;
                wmma::fragment<wmma::matrix_b, 16, 16, 16, half, wmma::col_major> bh;
                wmma::load_matrix_sync(ah, &Qh[(rg * 16) * QP + k16], QP);
                wmma::load_matrix_sync(bh, &Kh[(cg * 16) * KP + k16], KP);
                wmma::mma_sync(sf, ah, bh, sf);
            }
            wmma::store_matrix_sync(&Ssm[(rg * 16) * SP + cg * 16], sf, SP,
                                    wmma::mem_row_major);
        }
        __syncthreads();         // B2: Ssm visible; Kh free
        // p = exp(scale*s + maskterm)  (no max subtraction; scores are O(5))
        {
            float ls = 0.f;
#pragma unroll
            for (int i = 0; i < 8; i += 2) {
                float p0 = __expf(Ssm[rrow * SP + cbase + i]     * 0.0625f + mt[cbase + i]);
                float p1 = __expf(Ssm[rrow * SP + cbase + i + 1] * 0.0625f + mt[cbase + i + 1]);
                ls += p0 + p1;
                *(__half2*)&Ph[rrow * PP + cbase + i] = __floats2half2_rn(p0, p1);
            }
            ls += __shfl_xor_sync(0xffffffffu, ls, 1);
            ls += __shfl_xor_sync(0xffffffffu, ls, 2);
            l_run += ls;
        }
        CP_WAIT(0);              // V resident
        __syncthreads();         // B3: Ph/Vh visible
        // prefetch next K (overlaps PV MMA)
        if (kt + 1 < NT) {
            const f16* kh = qkv + (size_t)(kt + 1) * KT * F3 + 256;
#pragma unroll
            for (int it = 0; it < 4; it++) {
                int idx = tid + it * 256;
                int r = idx >> 5, c8 = (idx & 31) * 8;
                cpa16(&Kh[r * KP + c8], &kh[(size_t)r * F3 + c8]);
            }
            CP_COMMIT();
        }
        // O += P @ V
#pragma unroll
        for (int kk = 0; kk < KT; kk += 16) {
            wmma::fragment<wmma::matrix_a, 16, 16, 16, half, wmma::row_major> pah;
            wmma::load_matrix_sync(pah, &Ph[(rg * 16) * PP + kk], PP);
#pragma unroll
            for (int j = 0; j < 8; j++) {
                wmma::fragment<wmma::matrix_b, 16, 16, 16, half, wmma::row_major> vbh;
                wmma::load_matrix_sync(vbh, &Vh[kk * KP + cg * 128 + j * 16], KP);
                wmma::mma_sync(of[j], pah, vbh, of[j]);
            }
        }
        // no barrier here: B1 of next iter orders Vh/Ssm/mt reuse
    }

    __syncthreads();             // all PV MMAs done before Ost aliases Q/K/V
#pragma unroll
    for (int j = 0; j < 8; j++)
        wmma::store_matrix_sync(&Ost[(rg * 16) * OP + cg * 128 + j * 16], of[j], OP,
                                wmma::mem_row_major);
    __syncthreads();
    if (q0 + rrow < K_len) {
        float inv = 1.0f / l_run;
        size_t obase = (rowbase + q0 + rrow) * HDdim + (size_t)(tid & 3) * 64;
        int sbi = rrow * OP + (tid & 3) * 64;
#pragma unroll
        for (int c = 0; c < 64; c += 2)
            *(__half2*)&g_ctxh[obase + c] =
                __floats2half2_rn(Ost[sbi + c] * inv, Ost[sbi + c + 1] * inv);
    }
}

// ---------------- 6) FF GEMM + scatter-add ------------------------------------
__global__ void __launch_bounds__(256) k_ff(const float* __restrict__ bff,
                                            float* __restrict__ out)
{
    int K_len = g_maxlen;
    int row0 = blockIdx.y * 64; if (row0 >= K_len) return;
    int eb = blockIdx.z; int e = eb / Bdim, b = eb % Bdim;
    int col0 = blockIdx.x * 128;

    __shared__ __align__(16) unsigned char sraw[SRAW_BYTES];
    __shared__ int rows[64];
    __shared__ int scat[64];
    float* Cs = (float*)sraw;

    int tid = threadIdx.x;
    if (tid < 64) {
        int r = min(row0 + tid, K_len - 1);
        rows[tid] = r;
        scat[tid] = g_sid[eb * KMAXd + r];
    }
    __syncthreads();

    int wid = tid >> 5;
    int wr = wid >> 2, wc = wid & 3;

    wmma::fragment<wmma::accumulator, 16, 16, 16, float> acc[2][2];
#pragma unroll
    for (int i = 0; i < 2; i++)
#pragma unroll
        for (int j = 0; j < 2; j++) wmma::fill_fragment(acc[i][j], 0.f);

    const f16* Ag  = g_ctxh + (size_t)eb * KMAXd * HDdim;
    const f16* Bhg = g_Wfh + (size_t)e * HDdim * Ddim;
    const int T = HDdim / 32;

    g_issue(gstage(sraw, 0), tid, Ag, rows, HDdim, 0, Bhg, Ddim, col0);
    CP_COMMIT();
    for (int t = 0; t < T; t++) {
        if (t + 1 < T) {
            g_issue(gstage(sraw, (t + 1) & 1), tid, Ag, rows, HDdim, (t + 1) * 32,
                    Bhg, Ddim, col0);
            CP_COMMIT();
            CP_WAIT(1);
        } else {
            CP_WAIT(0);
        }
        __syncthreads();
        g_comp(gstage(sraw, t & 1), wr, wc, acc);
        __syncthreads();
    }

#pragma unroll
    for (int i = 0; i < 2; i++)
#pragma unroll
        for (int j = 0; j < 2; j++)
            wmma::store_matrix_sync(&Cs[(wr * 32 + i * 16) * CPITCH + wc * 32 + j * 16],
                                    acc[i][j], CPITCH, wmma::mem_row_major);
    __syncthreads();
    for (int idx = tid; idx < 64 * 128; idx += 256) {
        int r = idx >> 7, c = idx & 127;
        if (row0 + r < K_len) {
            atomicAdd(&out[((size_t)b * Sdim + scat[r]) * Ddim + col0 + c],
                      Cs[r * CPITCH + c] + bff[col0 + c]);
        }
    }
}

// ---------------- launch -----------------------------------------------------
extern "C" void kernel_launch(void* const* d_in, const int* in_sizes, int n_in,
                              void* d_out, int out_size)
{
    const float* X    = (const float*)d_in[0];
    const float* mask = (const float*)d_in[1];
    const float* wg   = (const float*)d_in[2];
    const float* bg   = (const float*)d_in[3];
    const float* Wqkv = (const float*)d_in[4];
    const float* bqkv = (const float*)d_in[5];
    const float* Wff  = (const float*)d_in[6];
    const float* bff  = (const float*)d_in[7];
    float* out = (float*)d_out;

    cudaFuncSetAttribute(k_attn2, cudaFuncAttributeMaxDynamicSharedMemorySize,
                         ATTN_SMEM);

    cudaMemsetAsync(out, 0, (size_t)out_size * sizeof(float));

    f16 *xh, *wqh, *wfh;
    int* maxlen_addr;
    cudaGetSymbolAddress((void**)&xh, g_Xh);
    cudaGetSymbolAddress((void**)&wqh, g_Wqh);
    cudaGetSymbolAddress((void**)&wfh, g_Wfh);
    cudaGetSymbolAddress((void**)&maxlen_addr, g_maxlen);
    cudaMemsetAsync(maxlen_addr, 0, sizeof(int));

    size_t nwq = (size_t)Edim * Ddim * F3 / 4;
    size_t nwf = (size_t)Edim * HDdim * Ddim / 4;
    k_cvtH<<<(unsigned)((nwq + 255) / 256), 256>>>(Wqkv, wqh, nwq);
    k_cvtH<<<(unsigned)((nwf + 255) / 256), 256>>>(Wff,  wfh, nwf);

    k_gate<<<Bdim * Sdim, 128>>>(X, wg, bg, xh);
    k_count<<<EB, 256>>>();
    k_build<<<EB, 256>>>();
    k_rtab<<<KMAXd, 512>>>();
    k_qkv<<<dim3(F3 / 128, Sdim / 64, EB), 256>>>(bqkv);
    k_attn2<<<dim3(Sdim / QT, EB), 256, ATTN_SMEM>>>(mask);
    k_ff<<<dim3(Ddim / 128, Sdim / 64, EB), 256>>>(bff, out);
}

// round 15
// speedup vs baseline: 1.1625x; 1.1625x over previous
#include <cuda_runtime.h>
#include <cuda_fp16.h>
#include <mma.h>
#include <math.h>
#include <stdint.h>

using namespace nvcuda;

#define Bdim  4
#define Sdim  2048
#define Ddim  2048
#define Edim  8
#define HDdim 256
#define F3    768
#define KMAXd 2048
#define EB    (Edim*Bdim)

typedef __half f16;

// ---------------- scratch (device globals; no allocations allowed) ----------
__device__ f16   g_qkvh[(size_t)EB * KMAXd * F3];  // post-rope [qf|kf|v] fp16
__device__ float g_S[(size_t)EB * KMAXd * KMAXd];  // attention scores scratch
__device__ f16   g_ctxh[(size_t)EB * KMAXd * HDdim];
__device__ f16   g_Xh[(size_t)Bdim * Sdim * Ddim];
__device__ f16   g_Wqh[(size_t)Edim * Ddim * F3];
__device__ f16   g_Wfh[(size_t)Edim * HDdim * Ddim];
__device__ float g_tcos[KMAXd * 512];
__device__ float g_tsin[KMAXd * 512];
__device__ int   g_sid[EB * KMAXd];
__device__ int   g_cnt[EB];
__device__ int   g_maxlen;
__device__ unsigned char g_emask[Bdim * Sdim];

// ---------------- cp.async helpers ------------------------------------------
__device__ __forceinline__ void cpa16(void* smem, const void* gmem)
{
    uint32_t s = (uint32_t)__cvta_generic_to_shared(smem);
    asm volatile("cp.async.cg.shared.global [%0], [%1], 16;\n" :: "r"(s), "l"(gmem));
}
#define CP_COMMIT() asm volatile("cp.async.commit_group;\n" ::: "memory")
#define CP_WAIT(n)  asm volatile("cp.async.wait_group %0;\n" :: "n"(n) : "memory")

// ---------------- 0b) fp32 -> fp16 single (weights) ---------------------------
__global__ void k_cvtH(const float* __restrict__ src, f16* __restrict__ h, size_t n4)
{
    size_t i = (size_t)blockIdx.x * blockDim.x + threadIdx.x;
    if (i >= n4) return;
    float4 v = reinterpret_cast<const float4*>(src)[i];
    __half2 h01 = __floats2half2_rn(v.x, v.y);
    __half2 h23 = __floats2half2_rn(v.z, v.w);
    reinterpret_cast<uint2*>(h)[i] = make_uint2(*(uint32_t*)&h01, *(uint32_t*)&h23);
}

// ---------------- 0c) rope tables (only K_len rows; fp32 sincos) -------------
__global__ void k_rtab()
{
    int k = blockIdx.x;
    if (k >= g_maxlen) return;
    int j = threadIdx.x;
    double freq = exp(((double)(-2 * j) / 1024.0) * log(10000.0));
    float ang = (float)k * (float)freq;
    float ss, cc;
    sincosf(ang, &ss, &cc);
    g_tcos[k * 512 + j] = cc;
    g_tsin[k * 512 + j] = ss;
}

// ---------------- 1) gate logits + top-2 mask + fused X->fp16 (scalar, proven)
__global__ void k_gate(const float* __restrict__ X,
                       const float* __restrict__ wg,
                       const float* __restrict__ bg,
                       f16* __restrict__ xh)
{
    int bs = blockIdx.x;
    const float* xr = X + (size_t)bs * Ddim;
    f16* xo = xh + (size_t)bs * Ddim;
    float acc[8];
#pragma unroll
    for (int e = 0; e < 8; e++) acc[e] = 0.f;
    for (int d = threadIdx.x; d < Ddim; d += 128) {
        float xv = xr[d];
        xo[d] = __float2half_rn(xv);
        const float4* w = (const float4*)(wg + d * Edim);
        float4 w0 = w[0], w1 = w[1];
        acc[0] = fmaf(xv, w0.x, acc[0]); acc[1] = fmaf(xv, w0.y, acc[1]);
        acc[2] = fmaf(xv, w0.z, acc[2]); acc[3] = fmaf(xv, w0.w, acc[3]);
        acc[4] = fmaf(xv, w1.x, acc[4]); acc[5] = fmaf(xv, w1.y, acc[5]);
        acc[6] = fmaf(xv, w1.z, acc[6]); acc[7] = fmaf(xv, w1.w, acc[7]);
    }
#pragma unroll
    for (int e = 0; e < 8; e++)
#pragma unroll
        for (int off = 16; off; off >>= 1)
            acc[e] += __shfl_down_sync(0xffffffffu, acc[e], off);

    __shared__ float red[4][8];
    int wid = threadIdx.x >> 5, lane = threadIdx.x & 31;
    if (lane == 0) {
#pragma unroll
        for (int e = 0; e < 8; e++) red[wid][e] = acc[e];
    }
    __syncthreads();
    if (threadIdx.x == 0) {
        float v[8];
#pragma unroll
        for (int e = 0; e < 8; e++)
            v[e] = red[0][e] + red[1][e] + red[2][e] + red[3][e] + bg[e];
        int e1 = 0; float b1 = v[0];
#pragma unroll
        for (int e = 1; e < 8; e++) if (v[e] > b1) { b1 = v[e]; e1 = e; }
        int e2 = -1; float b2 = -3.0e38f;
#pragma unroll
        for (int e = 0; e < 8; e++) if (e != e1 && v[e] > b2) { b2 = v[e]; e2 = e; }
        g_emask[bs] = (unsigned char)((1u << e1) | (1u << e2));
    }
}

// ---------------- 2) per-(e,b) member counts + global max -------------------
__global__ void k_count()
{
    int eb = blockIdx.x; int e = eb / Bdim, b = eb % Bdim;
    int n = 0;
    for (int s = threadIdx.x; s < Sdim; s += 256)
        n += (g_emask[b * Sdim + s] >> e) & 1;
#pragma unroll
    for (int off = 16; off; off >>= 1) n += __shfl_down_sync(0xffffffffu, n, off);
    __shared__ int sm[8];
    int wid = threadIdx.x >> 5, lane = threadIdx.x & 31;
    if (lane == 0) sm[wid] = n;
    __syncthreads();
    if (threadIdx.x == 0) {
        int t = 0;
#pragma unroll
        for (int w = 0; w < 8; w++) t += sm[w];
        g_cnt[eb] = t;
        atomicMax(&g_maxlen, t);
    }
}

// ---------------- 3) build seq_ids ------------------------------------------
__global__ void k_build()
{
    int eb = blockIdx.x; int e = eb / Bdim, b = eb % Bdim;
    int pad = g_maxlen - g_cnt[eb];
    __shared__ int wsum[8];
    __shared__ int carry;
    if (threadIdx.x == 0) carry = 0;
    __syncthreads();
    int wid = threadIdx.x >> 5, lane = threadIdx.x & 31;
    for (int s0 = 0; s0 < Sdim; s0 += 256) {
        int s = s0 + threadIdx.x;
        int m = (g_emask[b * Sdim + s] >> e) & 1;
        unsigned bal = __ballot_sync(0xffffffffu, m);
        int mp_w = __popc(bal & ((1u << lane) - 1u));
        if (lane == 0) wsum[wid] = __popc(bal);
        __syncthreads();
        int pre = 0;
#pragma unroll
        for (int w = 0; w < 8; w++) if (w < wid) pre += wsum[w];
        int mp  = carry + pre + mp_w;
        int nmb = s - mp;
        bool sel = m || (nmb < pad);
        int pos  = mp + min(nmb, pad);
        if (sel) g_sid[eb * KMAXd + pos] = s;
        __syncthreads();
        if (threadIdx.x == 0) {
            int t = 0;
#pragma unroll
            for (int w = 0; w < 8; w++) t += wsum[w];
            carry += t;
        }
        __syncthreads();
    }
}

// ---------------- GEMM machinery: C[64x128], A & B single fp16, 2-stage ------
#define APITCH 40
#define BPITCH 136
#define CPITCH 132
#define GSTAGE 13824
#define SRAW_BYTES (64 * CPITCH * 4)

struct GT { f16 *A, *Bh; };
__device__ __forceinline__ GT gstage(unsigned char* base, int s)
{
    unsigned char* p = base + s * GSTAGE;
    GT t; t.A = (f16*)p; t.Bh = (f16*)(p + 5120);
    return t;
}

__device__ __forceinline__ void g_issue(
    GT t, int tid, const f16* __restrict__ Ag, const int* rows, int astr, int k0,
    const f16* __restrict__ Bhg, int bstr, int col0)
{
    {
        int row = tid >> 2, c8 = (tid & 3) * 8;
        cpa16(&t.A[row * APITCH + c8], Ag + (size_t)rows[row] * astr + k0 + c8);
    }
#pragma unroll
    for (int it = 0; it < 2; it++) {
        int idx = tid + it * 256;
        int row = idx >> 4, c8 = (idx & 15) * 8;
        cpa16(&t.Bh[row * BPITCH + c8], Bhg + (size_t)(k0 + row) * bstr + col0 + c8);
    }
}

__device__ __forceinline__ void g_comp(
    GT t, int wr, int wc,
    wmma::fragment<wmma::accumulator, 16, 16, 16, float> (&acc)[2][2])
{
#pragma unroll
    for (int kk = 0; kk < 32; kk += 16) {
        wmma::fragment<wmma::matrix_a, 16, 16, 16, half, wmma::row_major> a[2];
        wmma::fragment<wmma::matrix_b, 16, 16, 16, half, wmma::row_major> bh[2];
#pragma unroll
        for (int i = 0; i < 2; i++)
            wmma::load_matrix_sync(a[i], &t.A[(wr * 32 + i * 16) * APITCH + kk], APITCH);
#pragma unroll
        for (int j = 0; j < 2; j++)
            wmma::load_matrix_sync(bh[j], &t.Bh[kk * BPITCH + wc * 32 + j * 16], BPITCH);
#pragma unroll
        for (int i = 0; i < 2; i++)
#pragma unroll
            for (int j = 0; j < 2; j++)
                wmma::mma_sync(acc[i][j], a[i], bh[j], acc[i][j]);
    }
}

// ---------------- 4) QKV GEMM + fused rope epilogue (fp16 out) ----------------
__global__ void __launch_bounds__(256) k_qkv(const float* __restrict__ bq)
{
    int K_len = g_maxlen;
    int row0 = blockIdx.y * 64; if (row0 >= K_len) return;
    int eb = blockIdx.z; int e = eb / Bdim, b = eb % Bdim;
    int col0 = blockIdx.x * 128;

    __shared__ __align__(16) unsigned char sraw[SRAW_BYTES];
    __shared__ int sids[64];
    float* Cs = (float*)sraw;

    int tid = threadIdx.x;
    if (tid < 64) sids[tid] = g_sid[eb * KMAXd + min(row0 + tid, K_len - 1)];
    __syncthreads();

    int wid = tid >> 5;
    int wr = wid >> 2, wc = wid & 3;

    wmma::fragment<wmma::accumulator, 16, 16, 16, float> acc[2][2];
#pragma unroll
    for (int i = 0; i < 2; i++)
#pragma unroll
        for (int j = 0; j < 2; j++) wmma::fill_fragment(acc[i][j], 0.f);

    const f16* Ag  = g_Xh + (size_t)b * Sdim * Ddim;
    const f16* Bhg = g_Wqh + (size_t)e * Ddim * F3;
    const int T = Ddim / 32;

    g_issue(gstage(sraw, 0), tid, Ag, sids, Ddim, 0, Bhg, F3, col0);
    CP_COMMIT();
    for (int t = 0; t < T; t++) {
        if (t + 1 < T) {
            g_issue(gstage(sraw, (t + 1) & 1), tid, Ag, sids, Ddim, (t + 1) * 32,
                    Bhg, F3, col0);
            CP_COMMIT();
            CP_WAIT(1);
        } else {
            CP_WAIT(0);
        }
        __syncthreads();
        g_comp(gstage(sraw, t & 1), wr, wc, acc);
        __syncthreads();
    }

#pragma unroll
    for (int i = 0; i < 2; i++)
#pragma unroll
        for (int j = 0; j < 2; j++)
            wmma::store_matrix_sync(&Cs[(wr * 32 + i * 16) * CPITCH + wc * 32 + j * 16],
                                    acc[i][j], CPITCH, wmma::mem_row_major);
    __syncthreads();

    // fused: bias + rope + fp16 convert, with nope/pe half swap
    int blk = col0 >> 8;               // 0=q, 1=k, 2=v
    int halfsel = (col0 >> 7) & 1;
    int obase = blk * 256;
    const float* bqe = bq + e * F3 + col0;
    for (int idx = tid; idx < 64 * 64; idx += 256) {
        int r = idx >> 6, p = idx & 63;
        int grow = row0 + r;
        if (grow >= K_len) continue;
        float v0 = Cs[r * CPITCH + 2 * p]     + bqe[2 * p];
        float v1 = Cs[r * CPITCH + 2 * p + 1] + bqe[2 * p + 1];
        int outc;
        if (blk == 2) {
            outc = col0 + 2 * p;
        } else if (halfsel == 0) {
            outc = obase + 128 + 2 * p;
        } else {
            int ti = grow * 512 + e * 64 + p;
            float c = g_tcos[ti], s = g_tsin[ti];
            float r0 = v0 * c - v1 * s;
            float r1 = v0 * s + v1 * c;
            v0 = r0; v1 = r1;
            outc = obase + 2 * p;
        }
        size_t off = ((size_t)eb * KMAXd + grow) * F3 + outc;
        *(__half2*)&g_qkvh[off] = __floats2half2_rn(v0, v1);
    }
}

// ---------------- 5) attention: R13 2-pass + double-buffered cp.async K/V ----
// layout: Q@0 (33792) | KV0@33792 (16896) | KV1@50688 (16896) | S@67584 (9216)
//         | mt@76800 (2x128) -> 77056. pass B: Ph@0 (5120), Ost@5120 (66560).
#define QT 64
#define KT 32
#define QP 264
#define KP 264
#define SP 36
#define PP 40
#define OP 260
#define AQ   0
#define AK0  33792
#define AK1  50688
#define AS   67584
#define AMT  76800
#define APH  0
#define AO   5120
#define ATTN_SMEM 77056

// issue one 32x256 fp16 tile (16 KB) via cp.async
__device__ __forceinline__ void a_issue(f16* dst, const f16* src, int tid)
{
#pragma unroll
    for (int it = 0; it < 4; it++) {
        int idx = tid + it * 256;
        int r = idx >> 5, c8 = (idx & 31) * 8;
        cpa16(&dst[r * KP + c8], &src[(size_t)r * F3 + c8]);
    }
}

__global__ void __launch_bounds__(256) k_attn2(const float* __restrict__ mask)
{
    extern __shared__ unsigned char dsm[];
    int K_len = g_maxlen;
    int q0 = blockIdx.x * QT; if (q0 >= K_len) return;
    int eb = blockIdx.y; int b = eb % Bdim;
    int tid = threadIdx.x, wid = tid >> 5;
    int rg = wid & 3, cg = wid >> 2;

    f16* Qh = (f16*)(dsm + AQ);
    f16* KV0 = (f16*)(dsm + AK0);
    f16* KV1 = (f16*)(dsm + AK1);
    float* Ssm = (float*)(dsm + AS);
    float* mt  = (float*)(dsm + AMT);   // [2][32]
    f16* Ph = (f16*)(dsm + APH);
    float* Ost = (float*)(dsm + AO);

    const size_t rowbase = (size_t)eb * KMAXd;
    const f16* qkv = g_qkvh + rowbase * F3;

    // Q tile 64 x 256 (sync load; visible after first barrier)
    {
        const f16* qh = qkv + (size_t)q0 * F3;
#pragma unroll
        for (int it = 0; it < 8; it++) {
            int idx = tid + it * 256;
            int r = idx >> 5, c8 = (idx & 31) * 8;
            *(uint4*)&Qh[r * QP + c8] = *(const uint4*)&qh[(size_t)r * F3 + c8];
        }
    }

    int NT = (K_len + KT - 1) / KT;
    int rrow = tid >> 2, cbase = (tid & 3) * 8;
    float m_run = -3.0e38f;
    float* srow = g_S + ((size_t)eb * KMAXd + q0 + rrow) * KMAXd;

    // ---- pass A: S = Q @ K^T, double-buffered K ----
    a_issue(KV0, qkv + 256, tid);
    CP_COMMIT();
    for (int kt = 0; kt < NT; kt++) {
        if (tid < KT) {
            int k = kt * KT + tid;
            mt[(kt & 1) * 32 + tid] = (k < K_len)
                ? -1000000.0f * (1.0f - mask[b * Sdim + g_sid[eb * KMAXd + k]])
                : -1.0e30f;
        }
        CP_WAIT(0);
        __syncthreads();                   // B1: K(kt), mt(kt) visible
        if (kt + 1 < NT) {
            a_issue((kt & 1) ? KV0 : KV1,
                    qkv + (size_t)(kt + 1) * KT * F3 + 256, tid);
            CP_COMMIT();
        }
        {
            f16* Kh = (kt & 1) ? KV1 : KV0;
            wmma::fragment<wmma::accumulator, 16, 16, 16, float> sf;
            wmma::fill_fragment(sf, 0.f);
#pragma unroll
            for (int k16 = 0; k16 < 256; k16 += 16) {
                wmma::fragment<wmma::matrix_a, 16, 16, 16, half, wmma::row_major> ah;
                wmma::fragment<wmma::matrix_b, 16, 16, 16, half, wmma::col_major> bh;
                wmma::load_matrix_sync(ah, &Qh[(rg * 16) * QP + k16], QP);
                wmma::load_matrix_sync(bh, &Kh[(cg * 16) * KP + k16], KP);
                wmma::mma_sync(sf, ah, bh, sf);
            }
            wmma::store_matrix_sync(&Ssm[(rg * 16) * SP + cg * 16], sf, SP,
                                    wmma::mem_row_major);
        }
        __syncthreads();                   // B2: Ssm visible
        {
            const float* mtb = mt + (kt & 1) * 32;
            float sv[8]; float tmax = -3.0e38f;
#pragma unroll
            for (int i = 0; i < 8; i++) {
                sv[i] = Ssm[rrow * SP + cbase + i] * 0.0625f + mtb[cbase + i];
                tmax = fmaxf(tmax, sv[i]);
            }
            tmax = fmaxf(tmax, __shfl_xor_sync(0xffffffffu, tmax, 1));
            tmax = fmaxf(tmax, __shfl_xor_sync(0xffffffffu, tmax, 2));
            m_run = fmaxf(m_run, tmax);
            *(float4*)&srow[kt * KT + cbase]     = make_float4(sv[0], sv[1], sv[2], sv[3]);
            *(float4*)&srow[kt * KT + cbase + 4] = make_float4(sv[4], sv[5], sv[6], sv[7]);
        }
        // no barrier: next iter's B1 orders Ssm/mt/buffer reuse
    }

    // ---- pass B: p = exp(s - m); l sum; O = P@V, double-buffered V ----
    float l_run = 0.f;
    wmma::fragment<wmma::accumulator, 16, 16, 16, float> of[8];
#pragma unroll
    for (int j = 0; j < 8; j++) wmma::fill_fragment(of[j], 0.f);

    a_issue(KV0, qkv + 512, tid);
    CP_COMMIT();
    for (int kt = 0; kt < NT; kt++) {
        CP_WAIT(0);
        __syncthreads();                   // B1: V(kt) visible; prev MMA done
        if (kt + 1 < NT) {
            a_issue((kt & 1) ? KV0 : KV1,
                    qkv + (size_t)(kt + 1) * KT * F3 + 512, tid);
            CP_COMMIT();
        }
        {
            float4 v0 = *(const float4*)&srow[kt * KT + cbase];
            float4 v1 = *(const float4*)&srow[kt * KT + cbase + 4];
            float pv[8] = {v0.x, v0.y, v0.z, v0.w, v1.x, v1.y, v1.z, v1.w};
            float ls = 0.f;
#pragma unroll
            for (int i = 0; i < 8; i++) { pv[i] = __expf(pv[i] - m_run); ls += pv[i]; }
            ls += __shfl_xor_sync(0xffffffffu, ls, 1);
            ls += __shfl_xor_sync(0xffffffffu, ls, 2);
            l_run += ls;
#pragma unroll
            for (int i = 0; i < 8; i += 2)
                *(__half2*)&Ph[rrow * PP + cbase + i] =
                    __floats2half2_rn(pv[i], pv[i + 1]);
        }
        __syncthreads();                   // B2: Ph visible
        {
            f16* Vh = (kt & 1) ? KV1 : KV0;
#pragma unroll
            for (int kk = 0; kk < KT; kk += 16) {
                wmma::fragment<wmma::matrix_a, 16, 16, 16, half, wmma::row_major> pah;
                wmma::load_matrix_sync(pah, &Ph[(rg * 16) * PP + kk], PP);
#pragma unroll
                for (int j = 0; j < 8; j++) {
                    wmma::fragment<wmma::matrix_b, 16, 16, 16, half, wmma::row_major> vbh;
                    wmma::load_matrix_sync(vbh, &Vh[kk * KP + cg * 128 + j * 16], KP);
                    wmma::mma_sync(of[j], pah, vbh, of[j]);
                }
            }
        }
        // no barrier: next iter's B1 orders Ph/buffer reuse
    }

    __syncthreads();                       // PV MMAs done before Ost aliasing
#pragma unroll
    for (int j = 0; j < 8; j++)
        wmma::store_matrix_sync(&Ost[(rg * 16) * OP + cg * 128 + j * 16], of[j], OP,
                                wmma::mem_row_major);
    __syncthreads();
    if (q0 + rrow < K_len) {
        float inv = 1.0f / l_run;
        size_t obase = (rowbase + q0 + rrow) * HDdim + (size_t)(tid & 3) * 64;
        int sbi = rrow * OP + (tid & 3) * 64;
#pragma unroll
        for (int c = 0; c < 64; c += 2)
            *(__half2*)&g_ctxh[obase + c] =
                __floats2half2_rn(Ost[sbi + c] * inv, Ost[sbi + c + 1] * inv);
    }
}

// ---------------- 6) FF GEMM + scatter-add ------------------------------------
__global__ void __launch_bounds__(256) k_ff(const float* __restrict__ bff,
                                            float* __restrict__ out)
{
    int K_len = g_maxlen;
    int row0 = blockIdx.y * 64; if (row0 >= K_len) return;
    int eb = blockIdx.z; int e = eb / Bdim, b = eb % Bdim;
    int col0 = blockIdx.x * 128;

    __shared__ __align__(16) unsigned char sraw[SRAW_BYTES];
    __shared__ int rows[64];
    __shared__ int scat[64];
    float* Cs = (float*)sraw;

    int tid = threadIdx.x;
    if (tid < 64) {
        int r = min(row0 + tid, K_len - 1);
        rows[tid] = r;
        scat[tid] = g_sid[eb * KMAXd + r];
    }
    __syncthreads();

    int wid = tid >> 5;
    int wr = wid >> 2, wc = wid & 3;

    wmma::fragment<wmma::accumulator, 16, 16, 16, float> acc[2][2];
#pragma unroll
    for (int i = 0; i < 2; i++)
#pragma unroll
        for (int j = 0; j < 2; j++) wmma::fill_fragment(acc[i][j], 0.f);

    const f16* Ag  = g_ctxh + (size_t)eb * KMAXd * HDdim;
    const f16* Bhg = g_Wfh + (size_t)e * HDdim * Ddim;
    const int T = HDdim / 32;

    g_issue(gstage(sraw, 0), tid, Ag, rows, HDdim, 0, Bhg, Ddim, col0);
    CP_COMMIT();
    for (int t = 0; t < T; t++) {
        if (t + 1 < T) {
            g_issue(gstage(sraw, (t + 1) & 1), tid, Ag, rows, HDdim, (t + 1) * 32,
                    Bhg, Ddim, col0);
            CP_COMMIT();
            CP_WAIT(1);
        } else {
            CP_WAIT(0);
        }
        __syncthreads();
        g_comp(gstage(sraw, t & 1), wr, wc, acc);
        __syncthreads();
    }

#pragma unroll
    for (int i = 0; i < 2; i++)
#pragma unroll
        for (int j = 0; j < 2; j++)
            wmma::store_matrix_sync(&Cs[(wr * 32 + i * 16) * CPITCH + wc * 32 + j * 16],
                                    acc[i][j], CPITCH, wmma::mem_row_major);
    __syncthreads();
    for (int idx = tid; idx < 64 * 128; idx += 256) {
        int r = idx >> 7, c = idx & 127;
        if (row0 + r < K_len) {
            atomicAdd(&out[((size_t)b * Sdim + scat[r]) * Ddim + col0 + c],
                      Cs[r * CPITCH + c] + bff[col0 + c]);
        }
    }
}

// ---------------- launch -----------------------------------------------------
extern "C" void kernel_launch(void* const* d_in, const int* in_sizes, int n_in,
                              void* d_out, int out_size)
{
    const float* X    = (const float*)d_in[0];
    const float* mask = (const float*)d_in[1];
    const float* wg   = (const float*)d_in[2];
    const float* bg   = (const float*)d_in[3];
    const float* Wqkv = (const float*)d_in[4];
    const float* bqkv = (const float*)d_in[5];
    const float* Wff  = (const float*)d_in[6];
    const float* bff  = (const float*)d_in[7];
    float* out = (float*)d_out;

    cudaFuncSetAttribute(k_attn2, cudaFuncAttributeMaxDynamicSharedMemorySize,
                         ATTN_SMEM);

    cudaMemsetAsync(out, 0, (size_t)out_size * sizeof(float));

    f16 *xh, *wqh, *wfh;
    int* maxlen_addr;
    cudaGetSymbolAddress((void**)&xh, g_Xh);
    cudaGetSymbolAddress((void**)&wqh, g_Wqh);
    cudaGetSymbolAddress((void**)&wfh, g_Wfh);
    cudaGetSymbolAddress((void**)&maxlen_addr, g_maxlen);
    cudaMemsetAsync(maxlen_addr, 0, sizeof(int));

    size_t nwq = (size_t)Edim * Ddim * F3 / 4;
    size_t nwf = (size_t)Edim * HDdim * Ddim / 4;
    k_cvtH<<<(unsigned)((nwq + 255) / 256), 256>>>(Wqkv, wqh, nwq);
    k_cvtH<<<(unsigned)((nwf + 255) / 256), 256>>>(Wff,  wfh, nwf);

    k_gate<<<Bdim * Sdim, 128>>>(X, wg, bg, xh);
    k_count<<<EB, 256>>>();
    k_build<<<EB, 256>>>();
    k_rtab<<<KMAXd, 512>>>();
    k_qkv<<<dim3(F3 / 128, Sdim / 64, EB), 256>>>(bqkv);
    k_attn2<<<dim3(Sdim / QT, EB), 256, ATTN_SMEM>>>(mask);
    k_ff<<<dim3(Ddim / 128, Sdim / 64, EB), 256>>>(bff, out);
}